// round 1
// baseline (speedup 1.0000x reference)
#include <cuda_runtime.h>
#include <cuda_bf16.h>
#include <math.h>

// Problem constants
#define BATCH 4
#define SEQ   2048
#define NTOK  (BATCH * SEQ)        // 8192 tokens
#define DIM   1024                 // D
#define HID   4096                 // H
#define NEXP  8                    // E
#define TOPK  2                    // K
#define NPAIR (NTOK * TOPK)        // 16384 (token, expert) pairs

// ---------------- device scratch (static: no cudaMalloc allowed) -------------
__device__ int   g_count[NEXP];
__device__ int   g_fill[NEXP];
__device__ int   g_offset[NEXP];
__device__ int   g_top_i[NTOK * TOPK];
__device__ float g_top_v[NTOK * TOPK];
__device__ int   g_tok[NPAIR];     // pair slot -> token id
__device__ float g_wt[NPAIR];      // pair slot -> gate weight
__device__ int   g_slot[NTOK * TOPK]; // (token,k) -> pair slot
__device__ float g_h[(size_t)NPAIR * HID]; // 268 MB hidden activations
__device__ float g_y[(size_t)NPAIR * DIM]; // 67 MB per-pair outputs

// ---------------- init ----------------
__global__ void init_kernel() {
    int i = threadIdx.x;
    if (i < NEXP) { g_count[i] = 0; g_fill[i] = 0; }
}

// ---------------- gating: one warp per token ----------------
__global__ void gating_kernel(const float* __restrict__ x,
                              const float* __restrict__ Wg,
                              const float* __restrict__ bg) {
    int warp = (blockIdx.x * blockDim.x + threadIdx.x) >> 5;
    int lane = threadIdx.x & 31;
    if (warp >= NTOK) return;
    const float* xr = x + (size_t)warp * DIM;

    float acc[NEXP];
#pragma unroll
    for (int e = 0; e < NEXP; e++) acc[e] = 0.f;

    for (int d = lane; d < DIM; d += 32) {
        float xv = xr[d];
        const float* wr = Wg + d * NEXP;
#pragma unroll
        for (int e = 0; e < NEXP; e++) acc[e] += xv * wr[e];
    }
#pragma unroll
    for (int off = 16; off > 0; off >>= 1) {
#pragma unroll
        for (int e = 0; e < NEXP; e++)
            acc[e] += __shfl_xor_sync(0xFFFFFFFFu, acc[e], off);
    }
    if (lane == 0) {
        float logit[NEXP];
#pragma unroll
        for (int e = 0; e < NEXP; e++) logit[e] = acc[e] + bg[e];
        float mx = logit[0];
#pragma unroll
        for (int e = 1; e < NEXP; e++) mx = fmaxf(mx, logit[e]);
        float p[NEXP], s = 0.f;
#pragma unroll
        for (int e = 0; e < NEXP; e++) { p[e] = expf(logit[e] - mx); s += p[e]; }
        // top-2 (raw softmax probs as weights; ties -> lowest index like jax)
        int i0 = 0; float v0 = p[0];
#pragma unroll
        for (int e = 1; e < NEXP; e++) if (p[e] > v0) { v0 = p[e]; i0 = e; }
        int i1 = -1; float v1 = -1.f;
#pragma unroll
        for (int e = 0; e < NEXP; e++)
            if (e != i0 && p[e] > v1) { v1 = p[e]; i1 = e; }
        float inv = 1.f / s;
        g_top_i[2 * warp + 0] = i0;  g_top_v[2 * warp + 0] = v0 * inv;
        g_top_i[2 * warp + 1] = i1;  g_top_v[2 * warp + 1] = v1 * inv;
        atomicAdd(&g_count[i0], 1);
        atomicAdd(&g_count[i1], 1);
    }
}

// ---------------- tiny exclusive scan over 8 counts ----------------
__global__ void scan_kernel() {
    if (threadIdx.x == 0) {
        int off = 0;
        for (int e = 0; e < NEXP; e++) { g_offset[e] = off; off += g_count[e]; }
    }
}

// ---------------- scatter tokens into per-expert segments ----------------
__global__ void scatter_kernel() {
    int t = blockIdx.x * blockDim.x + threadIdx.x;
    if (t >= NTOK) return;
#pragma unroll
    for (int k = 0; k < TOPK; k++) {
        int e = g_top_i[2 * t + k];
        int pos = atomicAdd(&g_fill[e], 1);
        int s = g_offset[e] + pos;
        g_tok[s]  = t;
        g_wt[s]   = g_top_v[2 * t + k];
        g_slot[2 * t + k] = s;
    }
}

// ---------------- grouped GEMM tiles: 64x64x16, 256 thr, 4x4/thr -----------
#define BM 64
#define BN 64
#define BK 16

// GEMM1: h = relu(gather(x) @ W1[e] + b1[e]),  [rows_e, 1024] x [1024, 4096]
__global__ void __launch_bounds__(256) gemm1_kernel(
        const float* __restrict__ x,
        const float* __restrict__ W1,
        const float* __restrict__ b1) {
    int e = blockIdx.z;
    int rows = g_count[e];
    int m0 = blockIdx.y * BM;
    if (m0 >= rows) return;
    int n0 = blockIdx.x * BN;
    int base = g_offset[e];
    const float* Bp = W1 + (size_t)e * DIM * HID;

    __shared__ float As[BK][BM + 4];
    __shared__ float Bs[BK][BN];

    int tid = threadIdx.x;
    int mA = tid >> 2, kA = (tid & 3) * 4;            // A loader
    int kB = tid >> 4, nB = (tid & 15) * 4;           // B loader
    int ty = tid >> 4, tx = tid & 15;                 // output 4x4

    int mClamp = m0 + mA; if (mClamp > rows - 1) mClamp = rows - 1;
    const float* arow = x + (size_t)g_tok[base + mClamp] * DIM;

    float acc[4][4];
#pragma unroll
    for (int i = 0; i < 4; i++)
#pragma unroll
        for (int j = 0; j < 4; j++) acc[i][j] = 0.f;

    for (int k0 = 0; k0 < DIM; k0 += BK) {
        float4 av = *(const float4*)(arow + k0 + kA);
        float4 bv = *(const float4*)(Bp + (size_t)(k0 + kB) * HID + n0 + nB);
        __syncthreads();
        As[kA + 0][mA] = av.x; As[kA + 1][mA] = av.y;
        As[kA + 2][mA] = av.z; As[kA + 3][mA] = av.w;
        *(float4*)&Bs[kB][nB] = bv;
        __syncthreads();
#pragma unroll
        for (int k = 0; k < BK; k++) {
            float4 a = *(const float4*)&As[k][ty * 4];
            float4 b = *(const float4*)&Bs[k][tx * 4];
            acc[0][0] += a.x * b.x; acc[0][1] += a.x * b.y; acc[0][2] += a.x * b.z; acc[0][3] += a.x * b.w;
            acc[1][0] += a.y * b.x; acc[1][1] += a.y * b.y; acc[1][2] += a.y * b.z; acc[1][3] += a.y * b.w;
            acc[2][0] += a.z * b.x; acc[2][1] += a.z * b.y; acc[2][2] += a.z * b.z; acc[2][3] += a.z * b.w;
            acc[3][0] += a.w * b.x; acc[3][1] += a.w * b.y; acc[3][2] += a.w * b.z; acc[3][3] += a.w * b.w;
        }
    }
    int nbase = n0 + tx * 4;
    float4 bb = *(const float4*)&b1[e * HID + nbase];
#pragma unroll
    for (int i = 0; i < 4; i++) {
        int m = m0 + ty * 4 + i;
        if (m < rows) {
            float4 r;
            r.x = fmaxf(acc[i][0] + bb.x, 0.f);
            r.y = fmaxf(acc[i][1] + bb.y, 0.f);
            r.z = fmaxf(acc[i][2] + bb.z, 0.f);
            r.w = fmaxf(acc[i][3] + bb.w, 0.f);
            *(float4*)&g_h[(size_t)(base + m) * HID + nbase] = r;
        }
    }
}

// GEMM2: y = wt * (h @ W2[e] + b2[e]),  [rows_e, 4096] x [4096, 1024]
__global__ void __launch_bounds__(256) gemm2_kernel(
        const float* __restrict__ W2,
        const float* __restrict__ b2) {
    int e = blockIdx.z;
    int rows = g_count[e];
    int m0 = blockIdx.y * BM;
    if (m0 >= rows) return;
    int n0 = blockIdx.x * BN;
    int base = g_offset[e];
    const float* Bp = W2 + (size_t)e * HID * DIM;

    __shared__ float As[BK][BM + 4];
    __shared__ float Bs[BK][BN];

    int tid = threadIdx.x;
    int mA = tid >> 2, kA = (tid & 3) * 4;
    int kB = tid >> 4, nB = (tid & 15) * 4;
    int ty = tid >> 4, tx = tid & 15;

    int mClamp = m0 + mA; if (mClamp > rows - 1) mClamp = rows - 1;
    const float* arow = g_h + (size_t)(base + mClamp) * HID;

    float acc[4][4];
#pragma unroll
    for (int i = 0; i < 4; i++)
#pragma unroll
        for (int j = 0; j < 4; j++) acc[i][j] = 0.f;

    for (int k0 = 0; k0 < HID; k0 += BK) {
        float4 av = *(const float4*)(arow + k0 + kA);
        float4 bv = *(const float4*)(Bp + (size_t)(k0 + kB) * DIM + n0 + nB);
        __syncthreads();
        As[kA + 0][mA] = av.x; As[kA + 1][mA] = av.y;
        As[kA + 2][mA] = av.z; As[kA + 3][mA] = av.w;
        *(float4*)&Bs[kB][nB] = bv;
        __syncthreads();
#pragma unroll
        for (int k = 0; k < BK; k++) {
            float4 a = *(const float4*)&As[k][ty * 4];
            float4 b = *(const float4*)&Bs[k][tx * 4];
            acc[0][0] += a.x * b.x; acc[0][1] += a.x * b.y; acc[0][2] += a.x * b.z; acc[0][3] += a.x * b.w;
            acc[1][0] += a.y * b.x; acc[1][1] += a.y * b.y; acc[1][2] += a.y * b.z; acc[1][3] += a.y * b.w;
            acc[2][0] += a.z * b.x; acc[2][1] += a.z * b.y; acc[2][2] += a.z * b.z; acc[2][3] += a.z * b.w;
            acc[3][0] += a.w * b.x; acc[3][1] += a.w * b.y; acc[3][2] += a.w * b.z; acc[3][3] += a.w * b.w;
        }
    }
    int nbase = n0 + tx * 4;
    float4 bb = *(const float4*)&b2[e * DIM + nbase];
#pragma unroll
    for (int i = 0; i < 4; i++) {
        int m = m0 + ty * 4 + i;
        if (m < rows) {
            float wt = g_wt[base + m];
            float4 r;
            r.x = wt * (acc[i][0] + bb.x);
            r.y = wt * (acc[i][1] + bb.y);
            r.z = wt * (acc[i][2] + bb.z);
            r.w = wt * (acc[i][3] + bb.w);
            *(float4*)&g_y[(size_t)(base + m) * DIM + nbase] = r;
        }
    }
}

// ---------------- combine: out[t] = y[slot0] + y[slot1] ----------------
__global__ void combine_kernel(float* __restrict__ out) {
    int t = blockIdx.x;
    int s0 = g_slot[2 * t + 0];
    int s1 = g_slot[2 * t + 1];
    const float4* y0 = (const float4*)(g_y + (size_t)s0 * DIM);
    const float4* y1 = (const float4*)(g_y + (size_t)s1 * DIM);
    float4* o = (float4*)(out + (size_t)t * DIM);
    for (int i = threadIdx.x; i < DIM / 4; i += blockDim.x) {
        float4 a = y0[i], b = y1[i];
        float4 r; r.x = a.x + b.x; r.y = a.y + b.y; r.z = a.z + b.z; r.w = a.w + b.w;
        o[i] = r;
    }
}

// ---------------- launch ----------------
extern "C" void kernel_launch(void* const* d_in, const int* in_sizes, int n_in,
                              void* d_out, int out_size) {
    const float* x  = (const float*)d_in[0];   // [4,2048,1024]
    const float* Wg = (const float*)d_in[1];   // [1024,8]
    const float* bg = (const float*)d_in[2];   // [8]
    const float* W1 = (const float*)d_in[3];   // [8,1024,4096]
    const float* b1 = (const float*)d_in[4];   // [8,4096]
    const float* W2 = (const float*)d_in[5];   // [8,4096,1024]
    const float* b2 = (const float*)d_in[6];   // [8,1024]
    float* out = (float*)d_out;                // [4,2048,1024]

    init_kernel<<<1, 32>>>();
    gating_kernel<<<(NTOK * 32) / 256, 256>>>(x, Wg, bg);
    scan_kernel<<<1, 32>>>();
    scatter_kernel<<<(NTOK + 255) / 256, 256>>>();
    // GEMM1: grid (H/64, maxRowTiles=128, E)
    gemm1_kernel<<<dim3(HID / BN, NTOK / BM, NEXP), 256>>>(x, W1, b1);
    // GEMM2: grid (D/64, 128, E)
    gemm2_kernel<<<dim3(DIM / BN, NTOK / BM, NEXP), 256>>>(W2, b2);
    combine_kernel<<<NTOK, 256>>>(out);
}

// round 5
// speedup vs baseline: 3.5979x; 3.5979x over previous
#include <cuda_runtime.h>
#include <cuda.h>
#include <cuda_bf16.h>
#include <math.h>
#include <stdint.h>

// ---------------- problem constants ----------------
#define BATCH 4
#define SEQ   2048
#define NTOK  (BATCH * SEQ)        // 8192
#define DIM   1024
#define HID   4096
#define NEXP  8
#define TOPK  2
#define NPAIR (NTOK * TOPK)        // 16384
#define PADMAX 17408               // 16384 + 8*128 pad slack

// GEMM tiling (static smem, <48KB)
#define BM 128
#define BN 128
#define BK 16
#define ASTR 20                    // A smem row stride (floats)
#define BSTR 136                   // B smem row stride (floats)

// ---------------- device scratch ----------------
__device__ __align__(1024) float g_xg[(size_t)PADMAX * DIM];
__device__ __align__(1024) float g_h [(size_t)PADMAX * HID];
__device__ __align__(1024) float g_y [(size_t)PADMAX * DIM];
__device__ __align__(1024) float g_w1c[(size_t)NEXP * DIM * HID];
__device__ __align__(1024) float g_w2c[(size_t)NEXP * HID * DIM];
__device__ int   g_count[NEXP];
__device__ int   g_fill[NEXP];
__device__ int   g_poffset[NEXP];
__device__ int   g_tilecum[NEXP + 1];
__device__ int   g_top_i[NPAIR];
__device__ float g_top_v[NPAIR];
__device__ float g_wt[PADMAX];
__device__ int   g_slot[NPAIR];

// ---------------- helpers ----------------
__device__ __forceinline__ uint32_t smem_u32(const void* p) {
    uint32_t a;
    asm("{ .reg .u64 t; cvta.to.shared.u64 t, %1; cvt.u32.u64 %0, t; }" : "=r"(a) : "l"(p));
    return a;
}
__device__ __forceinline__ uint32_t f2tf(float f) {
    uint32_t u;
    asm("cvt.rna.tf32.f32 %0, %1;" : "=r"(u) : "f"(f));
    return u;
}
__device__ __forceinline__ void cp_async16(uint32_t sdst, const void* gsrc) {
    asm volatile("cp.async.cg.shared.global [%0], [%1], 16;"
                 :: "r"(sdst), "l"(gsrc) : "memory");
}
__device__ __forceinline__ void cp_commit() {
    asm volatile("cp.async.commit_group;" ::: "memory");
}
__device__ __forceinline__ void cp_wait0() {
    asm volatile("cp.async.wait_group 0;" ::: "memory");
}
__device__ __forceinline__ void mma_tf32(float* d, const uint32_t* a,
                                         uint32_t b0, uint32_t b1) {
    asm volatile(
        "mma.sync.aligned.m16n8k8.row.col.f32.tf32.tf32.f32 "
        "{%0,%1,%2,%3}, {%4,%5,%6,%7}, {%8,%9}, {%0,%1,%2,%3};"
        : "+f"(d[0]), "+f"(d[1]), "+f"(d[2]), "+f"(d[3])
        : "r"(a[0]), "r"(a[1]), "r"(a[2]), "r"(a[3]), "r"(b0), "r"(b1));
}

// ---------------- routing kernels ----------------
__global__ void init_kernel() {
    int i = threadIdx.x;
    if (i < NEXP) { g_count[i] = 0; g_fill[i] = 0; }
}

__global__ void gating_kernel(const float* __restrict__ x,
                              const float* __restrict__ Wg,
                              const float* __restrict__ bg) {
    int warp = (blockIdx.x * blockDim.x + threadIdx.x) >> 5;
    int lane = threadIdx.x & 31;
    if (warp >= NTOK) return;
    const float* xr = x + (size_t)warp * DIM;
    float acc[NEXP];
#pragma unroll
    for (int e = 0; e < NEXP; e++) acc[e] = 0.f;
    for (int d = lane; d < DIM; d += 32) {
        float xv = xr[d];
        const float* wr = Wg + d * NEXP;
#pragma unroll
        for (int e = 0; e < NEXP; e++) acc[e] += xv * wr[e];
    }
#pragma unroll
    for (int off = 16; off > 0; off >>= 1)
#pragma unroll
        for (int e = 0; e < NEXP; e++)
            acc[e] += __shfl_xor_sync(0xFFFFFFFFu, acc[e], off);
    if (lane == 0) {
        float logit[NEXP];
#pragma unroll
        for (int e = 0; e < NEXP; e++) logit[e] = acc[e] + bg[e];
        float mx = logit[0];
#pragma unroll
        for (int e = 1; e < NEXP; e++) mx = fmaxf(mx, logit[e]);
        float p[NEXP], s = 0.f;
#pragma unroll
        for (int e = 0; e < NEXP; e++) { p[e] = expf(logit[e] - mx); s += p[e]; }
        int i0 = 0; float v0 = p[0];
#pragma unroll
        for (int e = 1; e < NEXP; e++) if (p[e] > v0) { v0 = p[e]; i0 = e; }
        int i1 = -1; float v1 = -1.f;
#pragma unroll
        for (int e = 0; e < NEXP; e++)
            if (e != i0 && p[e] > v1) { v1 = p[e]; i1 = e; }
        float inv = 1.f / s;
        g_top_i[2 * warp + 0] = i0;  g_top_v[2 * warp + 0] = v0 * inv;
        g_top_i[2 * warp + 1] = i1;  g_top_v[2 * warp + 1] = v1 * inv;
        atomicAdd(&g_count[i0], 1);
        atomicAdd(&g_count[i1], 1);
    }
}

__global__ void scan_kernel() {
    if (threadIdx.x == 0) {
        int off = 0, tc = 0;
        for (int e = 0; e < NEXP; e++) {
            g_poffset[e] = off;
            g_tilecum[e] = tc;
            int t = (g_count[e] + BM - 1) / BM;
            tc += t;
            off += t * BM;
        }
        g_tilecum[NEXP] = tc;
    }
}

__global__ void scatter_kernel() {
    int t = blockIdx.x * blockDim.x + threadIdx.x;
    if (t >= NTOK) return;
#pragma unroll
    for (int k = 0; k < TOPK; k++) {
        int e = g_top_i[2 * t + k];
        int pos = atomicAdd(&g_fill[e], 1);
        int s = g_poffset[e] + pos;
        g_wt[s] = g_top_v[2 * t + k];
        g_slot[2 * t + k] = s;
    }
}

// gather x rows to padded slots, rounding to tf32 (rna)
__global__ void gather_kernel(const float* __restrict__ x) {
    int pair = blockIdx.x;
    int t = pair >> 1;
    int slot = g_slot[pair];
    const float4* src = (const float4*)(x + (size_t)t * DIM);
    uint4* dst = (uint4*)(g_xg + (size_t)slot * DIM);
    for (int i = threadIdx.x; i < DIM / 4; i += blockDim.x) {
        float4 v = src[i];
        uint4 u;
        u.x = f2tf(v.x); u.y = f2tf(v.y); u.z = f2tf(v.z); u.w = f2tf(v.w);
        dst[i] = u;
    }
}

// round weights to tf32 (rna), writing device globals directly
__global__ void conv_w1_kernel(const float4* __restrict__ in) {
    uint4* out = (uint4*)g_w1c;
    int n4 = NEXP * DIM * HID / 4;
    int i = blockIdx.x * blockDim.x + threadIdx.x;
    int stride = gridDim.x * blockDim.x;
    for (; i < n4; i += stride) {
        float4 v = in[i];
        uint4 u;
        u.x = f2tf(v.x); u.y = f2tf(v.y); u.z = f2tf(v.z); u.w = f2tf(v.w);
        out[i] = u;
    }
}
__global__ void conv_w2_kernel(const float4* __restrict__ in) {
    uint4* out = (uint4*)g_w2c;
    int n4 = NEXP * HID * DIM / 4;
    int i = blockIdx.x * blockDim.x + threadIdx.x;
    int stride = gridDim.x * blockDim.x;
    for (; i < n4; i += stride) {
        float4 v = in[i];
        uint4 u;
        u.x = f2tf(v.x); u.y = f2tf(v.y); u.z = f2tf(v.z); u.w = f2tf(v.w);
        out[i] = u;
    }
}

// ---------------- grouped GEMM: tf32 mma.sync, static smem double buffer ---
// C tile 128x128, 256 threads, 8 warps (2m x 4n), warp tile 64x32.
// STAGE1: A=g_xg, W=g_w1c, out=g_h (relu + tf32 round). else A=g_h, W=g_w2c, out=g_y (*wt).
template <int KDIM, int NTOT, bool STAGE1>
__global__ void __launch_bounds__(256) moe_gemm_kernel(const float* __restrict__ bias) {
    __shared__ float sA[2][BM][ASTR];
    __shared__ float sB[2][BK][BSTR];

    int mt = blockIdx.y;
    if (mt >= g_tilecum[NEXP]) return;
    int e = 0;
#pragma unroll
    for (int i = 0; i < NEXP - 1; i++)
        if (mt >= g_tilecum[i + 1]) e = i + 1;
    int rowbase = g_poffset[e] + (mt - g_tilecum[e]) * BM;
    int n0 = blockIdx.x * BN;

    const float* Abuf = STAGE1 ? g_xg : g_h;
    const float* Wbuf = STAGE1 ? g_w1c : g_w2c;
    float* outbuf     = STAGE1 ? g_h  : g_y;

    const float* Ag = Abuf + (size_t)rowbase * KDIM;
    const float* Bg = Wbuf + (size_t)e * KDIM * NTOT + n0;

    int tid = threadIdx.x;
    int wid = tid >> 5, lane = tid & 31;
    int wm = wid >> 2, wn = wid & 3;        // 2x4 warp grid
    int c = lane & 3, r = lane >> 2;

    // loader indices (2 x 16B chunks each for A and B)
    int a_row = tid >> 2, a_cj = (tid & 3) * 4;    // rows 0..63 (+64), cols 0..12
    int b_row = tid >> 5, b_cj = (tid & 31) * 4;   // rows 0..7 (+8), cols 0..124

    float acc[4][4][4];
#pragma unroll
    for (int i = 0; i < 4; i++)
#pragma unroll
        for (int j = 0; j < 4; j++)
#pragma unroll
            for (int q = 0; q < 4; q++) acc[i][j][q] = 0.f;

    constexpr int NIT = KDIM / BK;

    auto load_stage = [&](int it, int buf) {
        int k0 = it * BK;
#pragma unroll
        for (int j = 0; j < 2; j++) {
            int row = a_row + j * 64;
            cp_async16(smem_u32(&sA[buf][row][a_cj]),
                       Ag + (size_t)row * KDIM + k0 + a_cj);
        }
#pragma unroll
        for (int j = 0; j < 2; j++) {
            int row = b_row + j * 8;
            cp_async16(smem_u32(&sB[buf][row][b_cj]),
                       Bg + (size_t)(k0 + row) * NTOT + b_cj);
        }
        cp_commit();
    };

    load_stage(0, 0);

    int buf = 0;
    for (int it = 0; it < NIT; ++it) {
        cp_wait0();
        __syncthreads();
        if (it + 1 < NIT) load_stage(it + 1, buf ^ 1);

#pragma unroll
        for (int ks = 0; ks < 2; ks++) {
            int kc = ks * 8 + c;
            uint32_t a[4][4];
#pragma unroll
            for (int mf = 0; mf < 4; mf++) {
                int m = wm * 64 + mf * 16 + r;
                a[mf][0] = __float_as_uint(sA[buf][m][kc]);
                a[mf][1] = __float_as_uint(sA[buf][m + 8][kc]);
                a[mf][2] = __float_as_uint(sA[buf][m][kc + 4]);
                a[mf][3] = __float_as_uint(sA[buf][m + 8][kc + 4]);
            }
#pragma unroll
            for (int nf = 0; nf < 4; nf++) {
                int n = wn * 32 + nf * 8 + r;
                uint32_t b0 = __float_as_uint(sB[buf][kc][n]);
                uint32_t b1 = __float_as_uint(sB[buf][kc + 4][n]);
#pragma unroll
                for (int mf = 0; mf < 4; mf++)
                    mma_tf32(acc[mf][nf], a[mf], b0, b1);
            }
        }
        __syncthreads();
        buf ^= 1;
    }

    // ---- epilogue ----
    const float* brow = bias + (size_t)e * NTOT;
#pragma unroll
    for (int mf = 0; mf < 4; mf++) {
        int m = wm * 64 + mf * 16 + r;
        int grow0 = rowbase + m;
        int grow1 = grow0 + 8;
        float wt0 = 0.f, wt1 = 0.f;
        if (!STAGE1) { wt0 = g_wt[grow0]; wt1 = g_wt[grow1]; }
#pragma unroll
        for (int nf = 0; nf < 4; nf++) {
            int gcol = n0 + wn * 32 + nf * 8 + 2 * c;
            float bb0 = brow[gcol], bb1 = brow[gcol + 1];
            float v00 = acc[mf][nf][0] + bb0;
            float v01 = acc[mf][nf][1] + bb1;
            float v10 = acc[mf][nf][2] + bb0;
            float v11 = acc[mf][nf][3] + bb1;
            if (STAGE1) {
                uint2 u0, u1;
                u0.x = f2tf(fmaxf(v00, 0.f)); u0.y = f2tf(fmaxf(v01, 0.f));
                u1.x = f2tf(fmaxf(v10, 0.f)); u1.y = f2tf(fmaxf(v11, 0.f));
                *(uint2*)(outbuf + (size_t)grow0 * NTOT + gcol) = u0;
                *(uint2*)(outbuf + (size_t)grow1 * NTOT + gcol) = u1;
            } else {
                float2 o0, o1;
                o0.x = v00 * wt0; o0.y = v01 * wt0;
                o1.x = v10 * wt1; o1.y = v11 * wt1;
                *(float2*)(outbuf + (size_t)grow0 * NTOT + gcol) = o0;
                *(float2*)(outbuf + (size_t)grow1 * NTOT + gcol) = o1;
            }
        }
    }
}

// ---------------- combine ----------------
__global__ void combine_kernel(float* __restrict__ out) {
    int t = blockIdx.x;
    int s0 = g_slot[2 * t + 0];
    int s1 = g_slot[2 * t + 1];
    const float4* y0 = (const float4*)(g_y + (size_t)s0 * DIM);
    const float4* y1 = (const float4*)(g_y + (size_t)s1 * DIM);
    float4* o = (float4*)(out + (size_t)t * DIM);
    for (int i = threadIdx.x; i < DIM / 4; i += blockDim.x) {
        float4 a = y0[i], b = y1[i];
        float4 rr;
        rr.x = a.x + b.x; rr.y = a.y + b.y; rr.z = a.z + b.z; rr.w = a.w + b.w;
        o[i] = rr;
    }
}

// ---------------- host launch (NO runtime API calls except launches) -------
extern "C" void kernel_launch(void* const* d_in, const int* in_sizes, int n_in,
                              void* d_out, int out_size) {
    const float* x  = (const float*)d_in[0];
    const float* Wg = (const float*)d_in[1];
    const float* bg = (const float*)d_in[2];
    const float* W1 = (const float*)d_in[3];
    const float* b1 = (const float*)d_in[4];
    const float* W2 = (const float*)d_in[5];
    const float* b2 = (const float*)d_in[6];
    float* out = (float*)d_out;

    init_kernel<<<1, 32>>>();
    gating_kernel<<<(NTOK * 32) / 256, 256>>>(x, Wg, bg);
    scan_kernel<<<1, 32>>>();
    scatter_kernel<<<(NTOK + 255) / 256, 256>>>();
    gather_kernel<<<NPAIR, 128>>>(x);
    conv_w1_kernel<<<4096, 256>>>((const float4*)W1);
    conv_w2_kernel<<<4096, 256>>>((const float4*)W2);

    int mtiles = NPAIR / BM + NEXP;  // 136 worst case
    moe_gemm_kernel<DIM, HID, true><<<dim3(HID / BN, mtiles), 256>>>(b1);
    moe_gemm_kernel<HID, DIM, false><<<dim3(DIM / BN, mtiles), 256>>>(b2);

    combine_kernel<<<NTOK, 256>>>(out);
}